// round 14
// baseline (speedup 1.0000x reference)
#include <cuda_runtime.h>
#include <cuda_fp16.h>
#include <math.h>

// Problem constants
#define NB    16
#define NDIM  256
#define NPIX  4096
#define NBB   64

// ---------------- scratch ----------
__device__ unsigned g_yhl[(size_t)NB * NDIM * NPIX];     // packed fp16 hi/lo
__device__ unsigned g_qkvhl[(size_t)NBB * 192 * NPIX];   // q, softmaxed k, v (packed)
__device__ float    g_MZ[4096];                          // M + log(Z) per q column
__device__ float    g_ctx[(size_t)NBB * 4 * 16 * 16];    // un-normalized context
__device__ unsigned g_aohl[(size_t)NBB * 64 * NPIX];     // packed, scrambled layout
__device__ unsigned g_wchl[256 * 256];                   // fused proj+final weight (packed)
__device__ float    g_cb[256];
__device__ unsigned g_wqhl[192 * 64];                    // qkv weight (packed)

// ---------------- helpers ----------
__device__ __forceinline__ unsigned pack_h2(__half a, __half b) {
    return (unsigned)__half_as_ushort(a) | ((unsigned)__half_as_ushort(b) << 16);
}
__device__ __forceinline__ unsigned packhl(float v) {
    __half h = __float2half_rn(v);
    __half l = __float2half_rn(v - __half2float(h));
    return pack_h2(h, l);
}
__device__ __forceinline__ float unpackf(unsigned u) {
    return __half2float(__ushort_as_half((unsigned short)(u & 0xffff)))
         + __half2float(__ushort_as_half((unsigned short)(u >> 16)));
}
__device__ __forceinline__ void mma16816(float* d, const unsigned* a, const unsigned* b) {
    asm volatile(
        "mma.sync.aligned.m16n8k16.row.col.f32.f16.f16.f32 "
        "{%0,%1,%2,%3}, {%4,%5,%6,%7}, {%8,%9}, {%0,%1,%2,%3};"
        : "+f"(d[0]), "+f"(d[1]), "+f"(d[2]), "+f"(d[3])
        : "r"(a[0]), "r"(a[1]), "r"(a[2]), "r"(a[3]), "r"(b[0]), "r"(b[1]));
}
__device__ __forceinline__ unsigned smem_u32(const void* p) {
    return (unsigned)__cvta_generic_to_shared(p);
}
#define CP16(dst, src) asm volatile("cp.async.ca.shared.global [%0], [%1], 16;" :: "r"(dst), "l"(src))
#define CP_COMMIT      asm volatile("cp.async.commit_group;")
#define CP_WAIT0       asm volatile("cp.async.wait_group 0;" ::: "memory")

// ---------------- merged prep: w_qkv split + Wc fusion --------------------
__global__ __launch_bounds__(256) void prep_kernel(
    const float* __restrict__ wq,
    const float* __restrict__ wp, const float* __restrict__ wf,
    const float* __restrict__ bp, const float* __restrict__ bf,
    const float* __restrict__ sw)
{
    int t = threadIdx.x;
    if (blockIdx.x < 48) {
        int i = blockIdx.x * 256 + t;
        if (i < 192 * 64) g_wqhl[i] = packhl(wq[i]);
        return;
    }
    __shared__ float sWf[256];
    __shared__ float red[256];
    int co = blockIdx.x - 48;
    sWf[t] = wf[co * 256 + t];
    __syncthreads();
    int br = t >> 6, e = t & 63;
    float s = sw[br];
    float acc = 0.f;
    #pragma unroll 8
    for (int ci = 0; ci < 64; ci++)
        acc += sWf[br * 64 + ci] * wp[ci * 64 + e];
    g_wchl[co * 256 + t] = packhl(acc * s);
    red[t] = s * sWf[t] * bp[e];
    __syncthreads();
    for (int s2 = 128; s2 > 0; s2 >>= 1) {
        if (t < s2) red[t] += red[t + s2];
        __syncthreads();
    }
    if (t == 0) g_cb[co] = bf[co] + red[0];
}

// ---------------- depthwise conv body (templated K) -----------------------
template<int K>
__device__ __forceinline__ void dwconv_body(
    const float* __restrict__ xp, const float* __restrict__ w,
    const float* __restrict__ bias, int c, unsigned* __restrict__ outp,
    float (*st)[80], float* ws)
{
    constexpr int R  = K / 2;
    constexpr int HT = 64 + 2 * R;
    int t = threadIdx.x;
    for (int i = t; i < HT * 80; i += 256) ((float*)st)[i] = 0.f;
    if (t < K * K) ws[t] = w[c * K * K + t];
    float bv = bias[c];
    __syncthreads();
    #pragma unroll
    for (int i = 0; i < 16; i++) {
        int p = t + i * 256;
        st[(p >> 6) + R][(p & 63) + R] = xp[p];
    }
    __syncthreads();

    int rowb = t >> 4, colb = (t & 15) * 4;
    #pragma unroll
    for (int it = 0; it < 4; it++) {
        int py = it * 16 + rowb;
        float a0 = 0.f, a1 = 0.f, a2 = 0.f, a3 = 0.f;
        #pragma unroll
        for (int u = 0; u < K; u++) {
            const float* p = &st[py + u][colb];
            float rv[12];
            {
                float4 r0 = *(const float4*)&p[0];
                float4 r1 = *(const float4*)&p[4];
                rv[0]=r0.x; rv[1]=r0.y; rv[2]=r0.z; rv[3]=r0.w;
                rv[4]=r1.x; rv[5]=r1.y; rv[6]=r1.z; rv[7]=r1.w;
                if (K + 3 > 8) {
                    float4 r2 = *(const float4*)&p[8];
                    rv[8]=r2.x; rv[9]=r2.y; rv[10]=r2.z; rv[11]=r2.w;
                }
            }
            const float* wrow = &ws[u * K];
            #pragma unroll
            for (int v = 0; v < K; v++) {
                float wv = wrow[v];
                a0 += rv[v    ] * wv;
                a1 += rv[v + 1] * wv;
                a2 += rv[v + 2] * wv;
                a3 += rv[v + 3] * wv;
            }
        }
        float r0 = st[py + R][colb + R    ];
        float r1 = st[py + R][colb + R + 1];
        float r2 = st[py + R][colb + R + 2];
        float r3 = st[py + R][colb + R + 3];
        uint4 o;
        o.x = packhl(fmaxf(a0 + bv + r0, 0.f));
        o.y = packhl(fmaxf(a1 + bv + r1, 0.f));
        o.z = packhl(fmaxf(a2 + bv + r2, 0.f));
        o.w = packhl(fmaxf(a3 + bv + r3, 0.f));
        *(uint4*)&outp[py * 64 + colb] = o;
    }
}

// ---------------- single-launch dwconv for all 4 branches -----------------
__global__ __launch_bounds__(256) void dwconv_all(
    const float* __restrict__ x,
    const float* __restrict__ w3, const float* __restrict__ b3,
    const float* __restrict__ w5, const float* __restrict__ b5,
    const float* __restrict__ w7, const float* __restrict__ b7,
    const float* __restrict__ w9, const float* __restrict__ b9)
{
    __shared__ float st[72][80];
    __shared__ float ws[81];
    int bc = blockIdx.x;
    int cg = bc & 255;
    int br = cg >> 6;
    int c  = cg & 63;
    size_t base = (size_t)bc * NPIX;
    const float* xp = x + base;
    unsigned* outp = g_yhl + base;
    switch (br) {
        case 0: dwconv_body<3>(xp, w3, b3, c, outp, st, ws); break;
        case 1: dwconv_body<5>(xp, w5, b5, c, outp, st, ws); break;
        case 2: dwconv_body<7>(xp, w7, b7, c, outp, st, ws); break;
        default: dwconv_body<9>(xp, w9, b9, c, outp, st, ws); break;
    }
}

// ---------------- tensor-core GEMM: cp.async double-buffered --------------
#define APS 132
__global__ __launch_bounds__(256) void gemm_cp(
    const unsigned* __restrict__ A, const unsigned* __restrict__ W,
    const float* __restrict__ bias,
    void* __restrict__ Cv, int K, long chunkA, long chunkC,
    int dosoftmax, int packout)
{
    __shared__ __align__(16) unsigned Ap[2][32][APS];
    __shared__ __align__(16) __half  Wh[2][64][40];

    int j0    = blockIdx.x * 64;
    int m0    = blockIdx.y * 128;
    int chunk = m0 >> 12;
    int mloc  = m0 & 4095;

    const unsigned* Ab = A + (size_t)chunk * chunkA + mloc;
    const unsigned* Wb = W + (size_t)j0 * K;
    float*    Cf = (float*)Cv    + (size_t)chunk * chunkC + mloc + (size_t)j0 * 4096;
    unsigned* Cp = (unsigned*)Cv + (size_t)chunk * chunkC + mloc + (size_t)j0 * 4096;

    int tid  = threadIdx.x;
    int wp   = tid >> 5;
    int lane = tid & 31;
    int g = lane >> 2, t4 = lane & 3;
    int warpm = wp & 3;
    int warpj = wp >> 2;
    int jf = tid >> 2;
    int kf = (tid & 3) * 8;

    float acc[2][4][4];
    #pragma unroll
    for (int mi = 0; mi < 2; mi++)
        #pragma unroll
        for (int ji = 0; ji < 4; ji++)
            #pragma unroll
            for (int cc = 0; cc < 4; cc++) acc[mi][ji][cc] = 0.f;

    int nchunk = K >> 5;

    #pragma unroll
    for (int i = 0; i < 4; i++) {
        int o = tid + 256 * i;
        int k = o >> 5, mg = (o & 31) * 4;
        CP16(smem_u32(&Ap[0][k][mg]), Ab + (size_t)k * 4096 + mg);
    }
    CP_COMMIT;
    uint4 wv0 = *(const uint4*)(Wb + (size_t)jf * K + kf);
    uint4 wv1 = *(const uint4*)(Wb + (size_t)jf * K + kf + 4);

    int buf = 0;
    for (int c = 0; c < nchunk; c++) {
        uint4 uh;
        uh.x = __byte_perm(wv0.x, wv0.y, 0x5410);
        uh.y = __byte_perm(wv0.z, wv0.w, 0x5410);
        uh.z = __byte_perm(wv1.x, wv1.y, 0x5410);
        uh.w = __byte_perm(wv1.z, wv1.w, 0x5410);
        *(uint4*)&Wh[buf][jf][kf] = uh;
        CP_WAIT0;
        __syncthreads();
        if (c + 1 < nchunk) {
            int k0n = (c + 1) * 32;
            #pragma unroll
            for (int i = 0; i < 4; i++) {
                int o = tid + 256 * i;
                int k = o >> 5, mg = (o & 31) * 4;
                CP16(smem_u32(&Ap[buf ^ 1][k][mg]), Ab + (size_t)(k0n + k) * 4096 + mg);
            }
            CP_COMMIT;
            wv0 = *(const uint4*)(Wb + (size_t)jf * K + k0n + kf);
            wv1 = *(const uint4*)(Wb + (size_t)jf * K + k0n + kf + 4);
        }
        #pragma unroll
        for (int kk = 0; kk < 32; kk += 16) {
            int k1 = kk + 2 * t4;
            unsigned ah[2][4], al[2][4];
            #pragma unroll
            for (int mi = 0; mi < 2; mi++) {
                int m = warpm * 32 + mi * 16 + g;
                unsigned w00 = Ap[buf][k1    ][m],     w01 = Ap[buf][k1 + 1][m];
                unsigned w10 = Ap[buf][k1    ][m + 8], w11 = Ap[buf][k1 + 1][m + 8];
                unsigned w20 = Ap[buf][k1 + 8][m],     w21 = Ap[buf][k1 + 9][m];
                unsigned w30 = Ap[buf][k1 + 8][m + 8], w31 = Ap[buf][k1 + 9][m + 8];
                ah[mi][0] = __byte_perm(w00, w01, 0x5410); al[mi][0] = __byte_perm(w00, w01, 0x7632);
                ah[mi][1] = __byte_perm(w10, w11, 0x5410); al[mi][1] = __byte_perm(w10, w11, 0x7632);
                ah[mi][2] = __byte_perm(w20, w21, 0x5410); al[mi][2] = __byte_perm(w20, w21, 0x7632);
                ah[mi][3] = __byte_perm(w30, w31, 0x5410); al[mi][3] = __byte_perm(w30, w31, 0x7632);
            }
            unsigned bh[4][2];
            #pragma unroll
            for (int ji = 0; ji < 4; ji++) {
                int j = warpj * 32 + ji * 8 + g;
                bh[ji][0] = *(const unsigned*)&Wh[buf][j][kk + 2 * t4];
                bh[ji][1] = *(const unsigned*)&Wh[buf][j][kk + 2 * t4 + 8];
            }
            #pragma unroll
            for (int mi = 0; mi < 2; mi++)
                #pragma unroll
                for (int ji = 0; ji < 4; ji++) {
                    mma16816(acc[mi][ji], ah[mi], bh[ji]);
                    mma16816(acc[mi][ji], al[mi], bh[ji]);
                }
        }
        __syncthreads();
        buf ^= 1;
    }

    float (*stage)[132] = (float(*)[132])Ap;
    int ksoft = dosoftmax && (j0 == 64);
    #pragma unroll
    for (int p = 0; p < 2; p++) {
        if (warpj == p) {
            #pragma unroll
            for (int mi = 0; mi < 2; mi++)
                #pragma unroll
                for (int ji = 0; ji < 4; ji++) {
                    int jr = ji * 8 + 2 * t4;
                    int m  = warpm * 32 + mi * 16 + g;
                    stage[jr    ][m    ] = acc[mi][ji][0];
                    stage[jr + 1][m    ] = acc[mi][ji][1];
                    stage[jr    ][m + 8] = acc[mi][ji][2];
                    stage[jr + 1][m + 8] = acc[mi][ji][3];
                }
        }
        __syncthreads();
        if (ksoft) {
            int hh = tid >> 7;
            int m  = tid & 127;
            float v[16];
            float mx = -3.4e38f;
            #pragma unroll
            for (int d = 0; d < 16; d++) { v[d] = stage[hh * 16 + d][m]; mx = fmaxf(mx, v[d]); }
            float ssum = 0.f;
            #pragma unroll
            for (int d = 0; d < 16; d++) { v[d] = __expf(v[d] - mx); ssum += v[d]; }
            float inv = 1.0f / ssum;
            #pragma unroll
            for (int d = 0; d < 16; d++)
                Cp[(size_t)(p * 32 + hh * 16 + d) * 4096 + m] = packhl(v[d] * inv);
        } else {
            #pragma unroll
            for (int r = 0; r < 4; r++) {
                int idx = r * 256 + tid;
                int jr  = idx >> 5;
                int m4  = (idx & 31) * 4;
                int jg  = p * 32 + jr;
                float bj = bias ? bias[j0 + jg] : 0.f;
                float4 v = *(const float4*)&stage[jr][m4];
                v.x += bj; v.y += bj; v.z += bj; v.w += bj;
                if (packout) {
                    uint4 u;
                    u.x = packhl(v.x); u.y = packhl(v.y);
                    u.z = packhl(v.z); u.w = packhl(v.w);
                    *(uint4*)(Cp + (size_t)jg * 4096 + m4) = u;
                } else {
                    *(float4*)(Cf + (size_t)jg * 4096 + m4) = v;
                }
            }
        }
        __syncthreads();
    }
}

// ---------------- merged qstats + context (independent now) ---------------
// blocks [0,4096): per-column MZ = M + log(sum exp(q - M))
// blocks [4096,4352): context[d][e] = sum_n k[n,d] v[n,e]  (NOT divided by Z)
__global__ __launch_bounds__(256) void statsctx_kernel()
{
    __shared__ float sh[16 * 128 * 2];
    int t = threadIdx.x;
    if (blockIdx.x < 4096) {
        float* red = sh;
        int col = blockIdx.x;
        int bb = col >> 6, j = col & 63;
        const unsigned* base = g_qkvhl + ((size_t)(bb * 192 + j)) * 4096;
        float v[16];
        float mx = -3.4e38f;
        #pragma unroll
        for (int i = 0; i < 16; i++) { v[i] = unpackf(base[t + i * 256]); mx = fmaxf(mx, v[i]); }
        red[t] = mx; __syncthreads();
        for (int s2 = 128; s2 > 0; s2 >>= 1) {
            if (t < s2) red[t] = fmaxf(red[t], red[t + s2]);
            __syncthreads();
        }
        mx = red[0]; __syncthreads();
        float sum = 0.f;
        #pragma unroll
        for (int i = 0; i < 16; i++) sum += __expf(v[i] - mx);
        red[t] = sum; __syncthreads();
        for (int s2 = 128; s2 > 0; s2 >>= 1) {
            if (t < s2) red[t] += red[t + s2];
            __syncthreads();
        }
        if (t == 0) g_MZ[col] = mx + __logf(red[0]);
        return;
    }
    float (*ks)[128] = (float(*)[128])sh;
    float (*vs)[128] = (float(*)[128])(sh + 16 * 128);
    int bh = blockIdx.x - 4096;
    int bb = bh >> 2, h = bh & 3;
    const unsigned* kb = g_qkvhl + ((size_t)(bb * 192 + 64  + h * 16)) * 4096;
    const unsigned* vb = g_qkvhl + ((size_t)(bb * 192 + 128 + h * 16)) * 4096;
    int d = t >> 4, e = t & 15;
    float acc = 0.f;
    for (int n0 = 0; n0 < 4096; n0 += 128) {
        #pragma unroll
        for (int i = 0; i < 2; i++) {
            int idx = t * 2 + i;
            int row = idx >> 5;
            int c4  = (idx & 31) * 4;
            uint4 ku = *(const uint4*)(kb + (size_t)row * 4096 + n0 + c4);
            uint4 vu = *(const uint4*)(vb + (size_t)row * 4096 + n0 + c4);
            ks[row][c4 + 0] = unpackf(ku.x); ks[row][c4 + 1] = unpackf(ku.y);
            ks[row][c4 + 2] = unpackf(ku.z); ks[row][c4 + 3] = unpackf(ku.w);
            vs[row][c4 + 0] = unpackf(vu.x); vs[row][c4 + 1] = unpackf(vu.y);
            vs[row][c4 + 2] = unpackf(vu.z); vs[row][c4 + 3] = unpackf(vu.w);
        }
        __syncthreads();
        #pragma unroll
        for (int q4 = 0; q4 < 32; q4++) {
            float4 a = *(const float4*)&ks[d][q4 * 4];
            float4 b = *(const float4*)&vs[e][q4 * 4];
            acc += a.x * b.x + a.y * b.y + a.z * b.z + a.w * b.w;
        }
        __syncthreads();
    }
    g_ctx[(size_t)bh * 256 + d * 16 + e] = acc;
}

// ---------------- attn out: ao = exp(q - MZ) @ ctx, reshape folded --------
__global__ __launch_bounds__(256) void attnout_kernel()
{
    __shared__ float cs[1024];
    __shared__ float ms[64];
    int bb = blockIdx.x >> 4;
    int nt = blockIdx.x & 15;
    int t  = threadIdx.x;
    int n  = nt * 256 + t;
    if (t < 64) ms[t] = g_MZ[bb * 64 + t];
    for (int i = t; i < 1024; i += 256) cs[i] = g_ctx[(size_t)bb * 1024 + i];
    __syncthreads();
    const unsigned* qb = g_qkvhl + (size_t)bb * 192 * 4096 + n;
    int cbase = 16 * (n & 3);
    int pbase = n >> 2;
    for (int h = 0; h < 4; h++) {
        float acc[16];
        #pragma unroll
        for (int e = 0; e < 16; e++) acc[e] = 0.f;
        #pragma unroll
        for (int d = 0; d < 16; d++) {
            int jc = h * 16 + d;
            float qv = __expf(unpackf(qb[(size_t)jc * 4096]) - ms[jc]);
            const float4* crow = (const float4*)&cs[jc * 16];
            #pragma unroll
            for (int e4 = 0; e4 < 4; e4++) {
                float4 cv = crow[e4];
                acc[e4 * 4 + 0] += qv * cv.x;
                acc[e4 * 4 + 1] += qv * cv.y;
                acc[e4 * 4 + 2] += qv * cv.z;
                acc[e4 * 4 + 3] += qv * cv.w;
            }
        }
        int np = h * 1024 + pbase;
        #pragma unroll
        for (int e = 0; e < 16; e++)
            g_aohl[((size_t)(bb * 64 + cbase + e)) * 4096 + np] = packhl(acc[e]);
    }
}

// ---------------- launch ---------------------------------------------------
extern "C" void kernel_launch(void* const* d_in, const int* in_sizes, int n_in,
                              void* d_out, int out_size)
{
    const float* x   = (const float*)d_in[0];
    const float* w3  = (const float*)d_in[1];
    const float* b3  = (const float*)d_in[2];
    const float* w5  = (const float*)d_in[3];
    const float* b5  = (const float*)d_in[4];
    const float* w7  = (const float*)d_in[5];
    const float* b7  = (const float*)d_in[6];
    const float* w9  = (const float*)d_in[7];
    const float* b9  = (const float*)d_in[8];
    const float* w_qkv   = (const float*)d_in[9];
    const float* w_proj  = (const float*)d_in[10];
    const float* b_proj  = (const float*)d_in[11];
    const float* w_final = (const float*)d_in[12];
    const float* b_final = (const float*)d_in[13];
    const float* scale_w = (const float*)d_in[14];
    float* out = (float*)d_out;

    unsigned *yp, *qkvp, *aop, *wcp;
    float *cbp;
    cudaGetSymbolAddress((void**)&yp,   g_yhl);
    cudaGetSymbolAddress((void**)&qkvp, g_qkvhl);
    cudaGetSymbolAddress((void**)&aop,  g_aohl);
    cudaGetSymbolAddress((void**)&wcp,  g_wchl);
    cudaGetSymbolAddress((void**)&cbp,  g_cb);
    unsigned* wqp;
    cudaGetSymbolAddress((void**)&wqp,  g_wqhl);

    // 0. merged weight prep
    prep_kernel<<<304, 256>>>(w_qkv, w_proj, w_final, b_proj, b_final, scale_w);

    // 1. all 4 depthwise conv branches in one launch -> g_yhl (packed)
    dwconv_all<<<NB * NDIM, 256>>>(x, w3, b3, w5, b5, w7, b7, w9, b9);

    // 2. QKV GEMM (cp.async double-buffered), fused K-softmax, packed out
    gemm_cp<<<dim3(3, 2048), 256>>>(yp, wqp, nullptr, qkvp,
                                    64, 64L * 4096, 192L * 4096, 1, 1);

    // 3. merged q-stats (MZ = M + logZ) + un-normalized context
    statsctx_kernel<<<4096 + 256, 256>>>();

    // 4. attention out -> g_aohl (packed, scrambled reshape layout)
    attnout_kernel<<<1024, 256>>>();

    // 5. fused proj+final GEMM: out = Wc @ ao + cbias (fp32 out)
    gemm_cp<<<dim3(4, 512), 256>>>(aop, wcp, cbp, out,
                                   256, 256L * 4096, 256L * 4096, 0, 0);
}

// round 16
// speedup vs baseline: 3.1830x; 3.1830x over previous
#include <cuda_runtime.h>
#include <cuda_fp16.h>
#include <math.h>

// Problem constants
#define NB    16
#define NDIM  256
#define NPIX  4096
#define NBB   64

// ---------------- scratch ----------
__device__ unsigned g_yhl[(size_t)NB * NDIM * NPIX];     // packed fp16 hi/lo
__device__ unsigned g_qkvhl[(size_t)NBB * 192 * NPIX];   // q, softmaxed k, v (packed)
__device__ float    g_MZ[4096];                          // M + log(Z) per q column
__device__ float    g_ctx[(size_t)NBB * 4 * 16 * 16];    // un-normalized context
__device__ unsigned g_aohl[(size_t)NBB * 64 * NPIX];     // packed, scrambled layout
__device__ unsigned g_wchl[256 * 256];                   // fused proj+final weight (packed)
__device__ float    g_cb[256];
__device__ unsigned g_wqhl[192 * 64];                    // qkv weight (packed)

// ---------------- helpers ----------
__device__ __forceinline__ unsigned pack_h2(__half a, __half b) {
    return (unsigned)__half_as_ushort(a) | ((unsigned)__half_as_ushort(b) << 16);
}
__device__ __forceinline__ unsigned packhl(float v) {
    __half h = __float2half_rn(v);
    __half l = __float2half_rn(v - __half2float(h));
    return pack_h2(h, l);
}
__device__ __forceinline__ float unpackf(unsigned u) {
    return __half2float(__ushort_as_half((unsigned short)(u & 0xffff)))
         + __half2float(__ushort_as_half((unsigned short)(u >> 16)));
}
__device__ __forceinline__ void mma16816(float* d, const unsigned* a, const unsigned* b) {
    asm volatile(
        "mma.sync.aligned.m16n8k16.row.col.f32.f16.f16.f32 "
        "{%0,%1,%2,%3}, {%4,%5,%6,%7}, {%8,%9}, {%0,%1,%2,%3};"
        : "+f"(d[0]), "+f"(d[1]), "+f"(d[2]), "+f"(d[3])
        : "r"(a[0]), "r"(a[1]), "r"(a[2]), "r"(a[3]), "r"(b[0]), "r"(b[1]));
}
__device__ __forceinline__ unsigned smem_u32(const void* p) {
    return (unsigned)__cvta_generic_to_shared(p);
}
#define CP16(dst, src) asm volatile("cp.async.ca.shared.global [%0], [%1], 16;" :: "r"(dst), "l"(src))
#define CP_COMMIT      asm volatile("cp.async.commit_group;")
#define CP_WAIT0       asm volatile("cp.async.wait_group 0;" ::: "memory")

// ---------------- merged prep: w_qkv split + Wc fusion --------------------
__global__ __launch_bounds__(256) void prep_kernel(
    const float* __restrict__ wq,
    const float* __restrict__ wp, const float* __restrict__ wf,
    const float* __restrict__ bp, const float* __restrict__ bf,
    const float* __restrict__ sw)
{
    int t = threadIdx.x;
    if (blockIdx.x < 48) {
        int i = blockIdx.x * 256 + t;
        if (i < 192 * 64) g_wqhl[i] = packhl(wq[i]);
        return;
    }
    __shared__ float sWf[256];
    __shared__ float red[256];
    int co = blockIdx.x - 48;
    sWf[t] = wf[co * 256 + t];
    __syncthreads();
    int br = t >> 6, e = t & 63;
    float s = sw[br];
    float acc = 0.f;
    #pragma unroll 8
    for (int ci = 0; ci < 64; ci++)
        acc += sWf[br * 64 + ci] * wp[ci * 64 + e];
    g_wchl[co * 256 + t] = packhl(acc * s);
    red[t] = s * sWf[t] * bp[e];
    __syncthreads();
    for (int s2 = 128; s2 > 0; s2 >>= 1) {
        if (t < s2) red[t] += red[t + s2];
        __syncthreads();
    }
    if (t == 0) g_cb[co] = bf[co] + red[0];
}

// ---------------- depthwise conv body (templated K) -----------------------
template<int K>
__device__ __forceinline__ void dwconv_body(
    const float* __restrict__ xp, const float* __restrict__ w,
    const float* __restrict__ bias, int c, unsigned* __restrict__ outp,
    float (*st)[80], float* ws)
{
    constexpr int R  = K / 2;
    constexpr int HT = 64 + 2 * R;
    int t = threadIdx.x;
    for (int i = t; i < HT * 80; i += 256) ((float*)st)[i] = 0.f;
    if (t < K * K) ws[t] = w[c * K * K + t];
    float bv = bias[c];
    __syncthreads();
    #pragma unroll
    for (int i = 0; i < 16; i++) {
        int p = t + i * 256;
        st[(p >> 6) + R][(p & 63) + R] = xp[p];
    }
    __syncthreads();

    int rowb = t >> 4, colb = (t & 15) * 4;
    #pragma unroll
    for (int it = 0; it < 4; it++) {
        int py = it * 16 + rowb;
        float a0 = 0.f, a1 = 0.f, a2 = 0.f, a3 = 0.f;
        #pragma unroll
        for (int u = 0; u < K; u++) {
            const float* p = &st[py + u][colb];
            float rv[12];
            {
                float4 r0 = *(const float4*)&p[0];
                float4 r1 = *(const float4*)&p[4];
                rv[0]=r0.x; rv[1]=r0.y; rv[2]=r0.z; rv[3]=r0.w;
                rv[4]=r1.x; rv[5]=r1.y; rv[6]=r1.z; rv[7]=r1.w;
                if (K + 3 > 8) {
                    float4 r2 = *(const float4*)&p[8];
                    rv[8]=r2.x; rv[9]=r2.y; rv[10]=r2.z; rv[11]=r2.w;
                }
            }
            const float* wrow = &ws[u * K];
            #pragma unroll
            for (int v = 0; v < K; v++) {
                float wv = wrow[v];
                a0 += rv[v    ] * wv;
                a1 += rv[v + 1] * wv;
                a2 += rv[v + 2] * wv;
                a3 += rv[v + 3] * wv;
            }
        }
        float r0 = st[py + R][colb + R    ];
        float r1 = st[py + R][colb + R + 1];
        float r2 = st[py + R][colb + R + 2];
        float r3 = st[py + R][colb + R + 3];
        uint4 o;
        o.x = packhl(fmaxf(a0 + bv + r0, 0.f));
        o.y = packhl(fmaxf(a1 + bv + r1, 0.f));
        o.z = packhl(fmaxf(a2 + bv + r2, 0.f));
        o.w = packhl(fmaxf(a3 + bv + r3, 0.f));
        *(uint4*)&outp[py * 64 + colb] = o;
    }
}

// ---------------- single-launch dwconv for all 4 branches -----------------
__global__ __launch_bounds__(256) void dwconv_all(
    const float* __restrict__ x,
    const float* __restrict__ w3, const float* __restrict__ b3,
    const float* __restrict__ w5, const float* __restrict__ b5,
    const float* __restrict__ w7, const float* __restrict__ b7,
    const float* __restrict__ w9, const float* __restrict__ b9)
{
    __shared__ float st[72][80];
    __shared__ float ws[81];
    int bc = blockIdx.x;
    int cg = bc & 255;
    int br = cg >> 6;
    int c  = cg & 63;
    size_t base = (size_t)bc * NPIX;
    const float* xp = x + base;
    unsigned* outp = g_yhl + base;
    switch (br) {
        case 0: dwconv_body<3>(xp, w3, b3, c, outp, st, ws); break;
        case 1: dwconv_body<5>(xp, w5, b5, c, outp, st, ws); break;
        case 2: dwconv_body<7>(xp, w7, b7, c, outp, st, ws); break;
        default: dwconv_body<9>(xp, w9, b9, c, outp, st, ws); break;
    }
}

// ---------------- tensor-core GEMM: cp.async double-buffered --------------
#define APS 132
__global__ __launch_bounds__(256) void gemm_cp(
    const unsigned* __restrict__ A, const unsigned* __restrict__ W,
    const float* __restrict__ bias,
    void* __restrict__ Cv, int K, long chunkA, long chunkC,
    int dosoftmax, int packout)
{
    __shared__ __align__(16) unsigned Ap[2][32][APS];
    __shared__ __align__(16) __half  Wh[2][64][40];

    int j0    = blockIdx.x * 64;
    int m0    = blockIdx.y * 128;
    int chunk = m0 >> 12;
    int mloc  = m0 & 4095;

    const unsigned* Ab = A + (size_t)chunk * chunkA + mloc;
    const unsigned* Wb = W + (size_t)j0 * K;
    float*    Cf = (float*)Cv    + (size_t)chunk * chunkC + mloc + (size_t)j0 * 4096;
    unsigned* Cp = (unsigned*)Cv + (size_t)chunk * chunkC + mloc + (size_t)j0 * 4096;

    int tid  = threadIdx.x;
    int wp   = tid >> 5;
    int lane = tid & 31;
    int g = lane >> 2, t4 = lane & 3;
    int warpm = wp & 3;
    int warpj = wp >> 2;
    int jf = tid >> 2;
    int kf = (tid & 3) * 8;

    float acc[2][4][4];
    #pragma unroll
    for (int mi = 0; mi < 2; mi++)
        #pragma unroll
        for (int ji = 0; ji < 4; ji++)
            #pragma unroll
            for (int cc = 0; cc < 4; cc++) acc[mi][ji][cc] = 0.f;

    int nchunk = K >> 5;

    #pragma unroll
    for (int i = 0; i < 4; i++) {
        int o = tid + 256 * i;
        int k = o >> 5, mg = (o & 31) * 4;
        CP16(smem_u32(&Ap[0][k][mg]), Ab + (size_t)k * 4096 + mg);
    }
    CP_COMMIT;
    uint4 wv0 = *(const uint4*)(Wb + (size_t)jf * K + kf);
    uint4 wv1 = *(const uint4*)(Wb + (size_t)jf * K + kf + 4);

    int buf = 0;
    for (int c = 0; c < nchunk; c++) {
        uint4 uh;
        uh.x = __byte_perm(wv0.x, wv0.y, 0x5410);
        uh.y = __byte_perm(wv0.z, wv0.w, 0x5410);
        uh.z = __byte_perm(wv1.x, wv1.y, 0x5410);
        uh.w = __byte_perm(wv1.z, wv1.w, 0x5410);
        *(uint4*)&Wh[buf][jf][kf] = uh;
        CP_WAIT0;
        __syncthreads();
        if (c + 1 < nchunk) {
            int k0n = (c + 1) * 32;
            #pragma unroll
            for (int i = 0; i < 4; i++) {
                int o = tid + 256 * i;
                int k = o >> 5, mg = (o & 31) * 4;
                CP16(smem_u32(&Ap[buf ^ 1][k][mg]), Ab + (size_t)(k0n + k) * 4096 + mg);
            }
            CP_COMMIT;
            wv0 = *(const uint4*)(Wb + (size_t)jf * K + k0n + kf);
            wv1 = *(const uint4*)(Wb + (size_t)jf * K + k0n + kf + 4);
        }
        #pragma unroll
        for (int kk = 0; kk < 32; kk += 16) {
            int k1 = kk + 2 * t4;
            unsigned ah[2][4], al[2][4];
            #pragma unroll
            for (int mi = 0; mi < 2; mi++) {
                int m = warpm * 32 + mi * 16 + g;
                unsigned w00 = Ap[buf][k1    ][m],     w01 = Ap[buf][k1 + 1][m];
                unsigned w10 = Ap[buf][k1    ][m + 8], w11 = Ap[buf][k1 + 1][m + 8];
                unsigned w20 = Ap[buf][k1 + 8][m],     w21 = Ap[buf][k1 + 9][m];
                unsigned w30 = Ap[buf][k1 + 8][m + 8], w31 = Ap[buf][k1 + 9][m + 8];
                ah[mi][0] = __byte_perm(w00, w01, 0x5410); al[mi][0] = __byte_perm(w00, w01, 0x7632);
                ah[mi][1] = __byte_perm(w10, w11, 0x5410); al[mi][1] = __byte_perm(w10, w11, 0x7632);
                ah[mi][2] = __byte_perm(w20, w21, 0x5410); al[mi][2] = __byte_perm(w20, w21, 0x7632);
                ah[mi][3] = __byte_perm(w30, w31, 0x5410); al[mi][3] = __byte_perm(w30, w31, 0x7632);
            }
            unsigned bh[4][2];
            #pragma unroll
            for (int ji = 0; ji < 4; ji++) {
                int j = warpj * 32 + ji * 8 + g;
                bh[ji][0] = *(const unsigned*)&Wh[buf][j][kk + 2 * t4];
                bh[ji][1] = *(const unsigned*)&Wh[buf][j][kk + 2 * t4 + 8];
            }
            #pragma unroll
            for (int mi = 0; mi < 2; mi++)
                #pragma unroll
                for (int ji = 0; ji < 4; ji++) {
                    mma16816(acc[mi][ji], ah[mi], bh[ji]);
                    mma16816(acc[mi][ji], al[mi], bh[ji]);
                }
        }
        __syncthreads();
        buf ^= 1;
    }

    float (*stage)[132] = (float(*)[132])Ap;
    int ksoft = dosoftmax && (j0 == 64);
    #pragma unroll
    for (int p = 0; p < 2; p++) {
        if (warpj == p) {
            #pragma unroll
            for (int mi = 0; mi < 2; mi++)
                #pragma unroll
                for (int ji = 0; ji < 4; ji++) {
                    int jr = ji * 8 + 2 * t4;
                    int m  = warpm * 32 + mi * 16 + g;
                    stage[jr    ][m    ] = acc[mi][ji][0];
                    stage[jr + 1][m    ] = acc[mi][ji][1];
                    stage[jr    ][m + 8] = acc[mi][ji][2];
                    stage[jr + 1][m + 8] = acc[mi][ji][3];
                }
        }
        __syncthreads();
        if (ksoft) {
            int hh = tid >> 7;
            int m  = tid & 127;
            float v[16];
            float mx = -3.4e38f;
            #pragma unroll
            for (int d = 0; d < 16; d++) { v[d] = stage[hh * 16 + d][m]; mx = fmaxf(mx, v[d]); }
            float ssum = 0.f;
            #pragma unroll
            for (int d = 0; d < 16; d++) { v[d] = __expf(v[d] - mx); ssum += v[d]; }
            float inv = 1.0f / ssum;
            #pragma unroll
            for (int d = 0; d < 16; d++)
                Cp[(size_t)(p * 32 + hh * 16 + d) * 4096 + m] = packhl(v[d] * inv);
        } else {
            #pragma unroll
            for (int r = 0; r < 4; r++) {
                int idx = r * 256 + tid;
                int jr  = idx >> 5;
                int m4  = (idx & 31) * 4;
                int jg  = p * 32 + jr;
                float bj = bias ? bias[j0 + jg] : 0.f;
                float4 v = *(const float4*)&stage[jr][m4];
                v.x += bj; v.y += bj; v.z += bj; v.w += bj;
                if (packout) {
                    uint4 u;
                    u.x = packhl(v.x); u.y = packhl(v.y);
                    u.z = packhl(v.z); u.w = packhl(v.w);
                    *(uint4*)(Cp + (size_t)jg * 4096 + m4) = u;
                } else {
                    *(float4*)(Cf + (size_t)jg * 4096 + m4) = v;
                }
            }
        }
        __syncthreads();
    }
}

// ---------------- q-stats: MZ = M + log(sum exp(q - M)) per column --------
__global__ __launch_bounds__(256) void qstats_kernel()
{
    __shared__ float red[256];
    int col = blockIdx.x;
    int bb = col >> 6, j = col & 63;
    const unsigned* base = g_qkvhl + ((size_t)(bb * 192 + j)) * 4096;
    int t = threadIdx.x;
    float v[16];
    float mx = -3.4e38f;
    #pragma unroll
    for (int i = 0; i < 16; i++) { v[i] = unpackf(base[t + i * 256]); mx = fmaxf(mx, v[i]); }
    red[t] = mx; __syncthreads();
    for (int s2 = 128; s2 > 0; s2 >>= 1) {
        if (t < s2) red[t] = fmaxf(red[t], red[t + s2]);
        __syncthreads();
    }
    mx = red[0]; __syncthreads();
    float sum = 0.f;
    #pragma unroll
    for (int i = 0; i < 16; i++) sum += __expf(v[i] - mx);
    red[t] = sum; __syncthreads();
    for (int s2 = 128; s2 > 0; s2 >>= 1) {
        if (t < s2) red[t] += red[t + s2];
        __syncthreads();
    }
    if (t == 0) g_MZ[col] = mx + __logf(red[0]);
}

// ---------------- context: C[d,e] = sum_n key[n,d] v[n,e] (un-normalized) -
// smem rows padded to 132 floats: lane e hits banks 4e..4e+3 -> conflict-free
__global__ __launch_bounds__(256) void context_kernel()
{
    __shared__ float ks[16][132];
    __shared__ float vs[16][132];
    int bh = blockIdx.x;
    int bb = bh >> 2, h = bh & 3;
    const unsigned* kb = g_qkvhl + ((size_t)(bb * 192 + 64  + h * 16)) * 4096;
    const unsigned* vb = g_qkvhl + ((size_t)(bb * 192 + 128 + h * 16)) * 4096;
    int t = threadIdx.x;
    int d = t >> 4, e = t & 15;
    float acc = 0.f;
    for (int n0 = 0; n0 < 4096; n0 += 128) {
        #pragma unroll
        for (int i = 0; i < 2; i++) {
            int idx = t * 2 + i;
            int row = idx >> 5;
            int c4  = (idx & 31) * 4;
            uint4 ku = *(const uint4*)(kb + (size_t)row * 4096 + n0 + c4);
            uint4 vu = *(const uint4*)(vb + (size_t)row * 4096 + n0 + c4);
            ks[row][c4 + 0] = unpackf(ku.x); ks[row][c4 + 1] = unpackf(ku.y);
            ks[row][c4 + 2] = unpackf(ku.z); ks[row][c4 + 3] = unpackf(ku.w);
            vs[row][c4 + 0] = unpackf(vu.x); vs[row][c4 + 1] = unpackf(vu.y);
            vs[row][c4 + 2] = unpackf(vu.z); vs[row][c4 + 3] = unpackf(vu.w);
        }
        __syncthreads();
        #pragma unroll
        for (int q4 = 0; q4 < 32; q4++) {
            float4 a = *(const float4*)&ks[d][q4 * 4];
            float4 b = *(const float4*)&vs[e][q4 * 4];
            acc += a.x * b.x + a.y * b.y + a.z * b.z + a.w * b.w;
        }
        __syncthreads();
    }
    g_ctx[(size_t)bh * 256 + d * 16 + e] = acc;
}

// ---------------- attn out: ao = exp(q - MZ) @ ctx, reshape folded --------
__global__ __launch_bounds__(256) void attnout_kernel()
{
    __shared__ float cs[1024];
    __shared__ float ms[64];
    int bb = blockIdx.x >> 4;
    int nt = blockIdx.x & 15;
    int t  = threadIdx.x;
    int n  = nt * 256 + t;
    if (t < 64) ms[t] = g_MZ[bb * 64 + t];
    for (int i = t; i < 1024; i += 256) cs[i] = g_ctx[(size_t)bb * 1024 + i];
    __syncthreads();
    const unsigned* qb = g_qkvhl + (size_t)bb * 192 * 4096 + n;
    int cbase = 16 * (n & 3);
    int pbase = n >> 2;
    for (int h = 0; h < 4; h++) {
        float acc[16];
        #pragma unroll
        for (int e = 0; e < 16; e++) acc[e] = 0.f;
        #pragma unroll
        for (int d = 0; d < 16; d++) {
            int jc = h * 16 + d;
            float qv = __expf(unpackf(qb[(size_t)jc * 4096]) - ms[jc]);
            const float4* crow = (const float4*)&cs[jc * 16];
            #pragma unroll
            for (int e4 = 0; e4 < 4; e4++) {
                float4 cv = crow[e4];
                acc[e4 * 4 + 0] += qv * cv.x;
                acc[e4 * 4 + 1] += qv * cv.y;
                acc[e4 * 4 + 2] += qv * cv.z;
                acc[e4 * 4 + 3] += qv * cv.w;
            }
        }
        int np = h * 1024 + pbase;
        #pragma unroll
        for (int e = 0; e < 16; e++)
            g_aohl[((size_t)(bb * 64 + cbase + e)) * 4096 + np] = packhl(acc[e]);
    }
}

// ---------------- launch ---------------------------------------------------
extern "C" void kernel_launch(void* const* d_in, const int* in_sizes, int n_in,
                              void* d_out, int out_size)
{
    const float* x   = (const float*)d_in[0];
    const float* w3  = (const float*)d_in[1];
    const float* b3  = (const float*)d_in[2];
    const float* w5  = (const float*)d_in[3];
    const float* b5  = (const float*)d_in[4];
    const float* w7  = (const float*)d_in[5];
    const float* b7  = (const float*)d_in[6];
    const float* w9  = (const float*)d_in[7];
    const float* b9  = (const float*)d_in[8];
    const float* w_qkv   = (const float*)d_in[9];
    const float* w_proj  = (const float*)d_in[10];
    const float* b_proj  = (const float*)d_in[11];
    const float* w_final = (const float*)d_in[12];
    const float* b_final = (const float*)d_in[13];
    const float* scale_w = (const float*)d_in[14];
    float* out = (float*)d_out;

    unsigned *yp, *qkvp, *aop, *wcp, *wqp;
    float *cbp;
    cudaGetSymbolAddress((void**)&yp,   g_yhl);
    cudaGetSymbolAddress((void**)&qkvp, g_qkvhl);
    cudaGetSymbolAddress((void**)&aop,  g_aohl);
    cudaGetSymbolAddress((void**)&wcp,  g_wchl);
    cudaGetSymbolAddress((void**)&wqp,  g_wqhl);
    cudaGetSymbolAddress((void**)&cbp,  g_cb);

    // 0. merged weight prep
    prep_kernel<<<304, 256>>>(w_qkv, w_proj, w_final, b_proj, b_final, scale_w);

    // 1. all 4 depthwise conv branches in one launch -> g_yhl (packed)
    dwconv_all<<<NB * NDIM, 256>>>(x, w3, b3, w5, b5, w7, b7, w9, b9);

    // 2. QKV GEMM (cp.async double-buffered), fused K-softmax, packed out
    gemm_cp<<<dim3(3, 2048), 256>>>(yp, wqp, nullptr, qkvp,
                                    64, 64L * 4096, 192L * 4096, 1, 1);

    // 3. q-stats: MZ = M + logZ
    qstats_kernel<<<4096, 256>>>();

    // 4. context (un-normalized, conflict-free smem)
    context_kernel<<<256, 256>>>();

    // 5. attention out -> g_aohl (packed, scrambled reshape layout)
    attnout_kernel<<<1024, 256>>>();

    // 6. fused proj+final GEMM: out = Wc @ ao + cbias (fp32 out)
    gemm_cp<<<dim3(4, 512), 256>>>(aop, wcp, cbp, out,
                                   256, 256L * 4096, 256L * 4096, 0, 0);
}

// round 17
// speedup vs baseline: 3.4462x; 1.0827x over previous
#include <cuda_runtime.h>
#include <cuda_fp16.h>
#include <math.h>

// Problem constants
#define NB    16
#define NDIM  256
#define NPIX  4096
#define NBB   64

// ---------------- scratch ----------
__device__ unsigned g_yhl[(size_t)NB * NDIM * NPIX];     // packed fp16 hi/lo
__device__ unsigned g_qkvhl[(size_t)NBB * 192 * NPIX];   // q, softmaxed k, v (packed)
__device__ float    g_MZ[4096];                          // M + log(Z) per q column
__device__ float    g_ctx[(size_t)NBB * 4 * 16 * 16];    // un-normalized context
__device__ unsigned g_aoh2[(size_t)NBB * 32 * NPIX];     // ao fp16 channel-pairs
__device__ unsigned g_wchl[256 * 256];                   // fused proj+final weight (packed)
__device__ float    g_cb[256];
__device__ unsigned g_wqhl[192 * 64];                    // qkv weight (packed)

// ---------------- helpers ----------
__device__ __forceinline__ unsigned pack_h2(__half a, __half b) {
    return (unsigned)__half_as_ushort(a) | ((unsigned)__half_as_ushort(b) << 16);
}
__device__ __forceinline__ unsigned packhl(float v) {
    __half h = __float2half_rn(v);
    __half l = __float2half_rn(v - __half2float(h));
    return pack_h2(h, l);
}
__device__ __forceinline__ float unpackf(unsigned u) {
    return __half2float(__ushort_as_half((unsigned short)(u & 0xffff)))
         + __half2float(__ushort_as_half((unsigned short)(u >> 16)));
}
__device__ __forceinline__ void mma16816(float* d, const unsigned* a, const unsigned* b) {
    asm volatile(
        "mma.sync.aligned.m16n8k16.row.col.f32.f16.f16.f32 "
        "{%0,%1,%2,%3}, {%4,%5,%6,%7}, {%8,%9}, {%0,%1,%2,%3};"
        : "+f"(d[0]), "+f"(d[1]), "+f"(d[2]), "+f"(d[3])
        : "r"(a[0]), "r"(a[1]), "r"(a[2]), "r"(a[3]), "r"(b[0]), "r"(b[1]));
}
__device__ __forceinline__ unsigned smem_u32(const void* p) {
    return (unsigned)__cvta_generic_to_shared(p);
}
#define CP16(dst, src) asm volatile("cp.async.ca.shared.global [%0], [%1], 16;" :: "r"(dst), "l"(src))
#define CP_COMMIT      asm volatile("cp.async.commit_group;")
#define CP_WAIT0       asm volatile("cp.async.wait_group 0;" ::: "memory")

// ---------------- merged prep: w_qkv split + Wc fusion --------------------
__global__ __launch_bounds__(256) void prep_kernel(
    const float* __restrict__ wq,
    const float* __restrict__ wp, const float* __restrict__ wf,
    const float* __restrict__ bp, const float* __restrict__ bf,
    const float* __restrict__ sw)
{
    int t = threadIdx.x;
    if (blockIdx.x < 48) {
        int i = blockIdx.x * 256 + t;
        if (i < 192 * 64) g_wqhl[i] = packhl(wq[i]);
        return;
    }
    __shared__ float sWf[256];
    __shared__ float red[256];
    int co = blockIdx.x - 48;
    sWf[t] = wf[co * 256 + t];
    __syncthreads();
    int br = t >> 6, e = t & 63;
    float s = sw[br];
    float acc = 0.f;
    #pragma unroll 8
    for (int ci = 0; ci < 64; ci++)
        acc += sWf[br * 64 + ci] * wp[ci * 64 + e];
    g_wchl[co * 256 + t] = packhl(acc * s);
    red[t] = s * sWf[t] * bp[e];
    __syncthreads();
    for (int s2 = 128; s2 > 0; s2 >>= 1) {
        if (t < s2) red[t] += red[t + s2];
        __syncthreads();
    }
    if (t == 0) g_cb[co] = bf[co] + red[0];
}

// ---------------- depthwise conv body (templated K) -----------------------
template<int K>
__device__ __forceinline__ void dwconv_body(
    const float* __restrict__ xp, const float* __restrict__ w,
    const float* __restrict__ bias, int c, unsigned* __restrict__ outp,
    float (*st)[80], float* ws)
{
    constexpr int R  = K / 2;
    constexpr int HT = 64 + 2 * R;
    int t = threadIdx.x;
    for (int i = t; i < HT * 80; i += 256) ((float*)st)[i] = 0.f;
    if (t < K * K) ws[t] = w[c * K * K + t];
    float bv = bias[c];
    __syncthreads();
    #pragma unroll
    for (int i = 0; i < 16; i++) {
        int p = t + i * 256;
        st[(p >> 6) + R][(p & 63) + R] = xp[p];
    }
    __syncthreads();

    int rowb = t >> 4, colb = (t & 15) * 4;
    #pragma unroll
    for (int it = 0; it < 4; it++) {
        int py = it * 16 + rowb;
        float a0 = 0.f, a1 = 0.f, a2 = 0.f, a3 = 0.f;
        #pragma unroll
        for (int u = 0; u < K; u++) {
            const float* p = &st[py + u][colb];
            float rv[12];
            {
                float4 r0 = *(const float4*)&p[0];
                float4 r1 = *(const float4*)&p[4];
                rv[0]=r0.x; rv[1]=r0.y; rv[2]=r0.z; rv[3]=r0.w;
                rv[4]=r1.x; rv[5]=r1.y; rv[6]=r1.z; rv[7]=r1.w;
                if (K + 3 > 8) {
                    float4 r2 = *(const float4*)&p[8];
                    rv[8]=r2.x; rv[9]=r2.y; rv[10]=r2.z; rv[11]=r2.w;
                }
            }
            const float* wrow = &ws[u * K];
            #pragma unroll
            for (int v = 0; v < K; v++) {
                float wv = wrow[v];
                a0 += rv[v    ] * wv;
                a1 += rv[v + 1] * wv;
                a2 += rv[v + 2] * wv;
                a3 += rv[v + 3] * wv;
            }
        }
        float r0 = st[py + R][colb + R    ];
        float r1 = st[py + R][colb + R + 1];
        float r2 = st[py + R][colb + R + 2];
        float r3 = st[py + R][colb + R + 3];
        uint4 o;
        o.x = packhl(fmaxf(a0 + bv + r0, 0.f));
        o.y = packhl(fmaxf(a1 + bv + r1, 0.f));
        o.z = packhl(fmaxf(a2 + bv + r2, 0.f));
        o.w = packhl(fmaxf(a3 + bv + r3, 0.f));
        *(uint4*)&outp[py * 64 + colb] = o;
    }
}

// ---------------- single-launch dwconv for all 4 branches -----------------
__global__ __launch_bounds__(256) void dwconv_all(
    const float* __restrict__ x,
    const float* __restrict__ w3, const float* __restrict__ b3,
    const float* __restrict__ w5, const float* __restrict__ b5,
    const float* __restrict__ w7, const float* __restrict__ b7,
    const float* __restrict__ w9, const float* __restrict__ b9)
{
    __shared__ float st[72][80];
    __shared__ float ws[81];
    int bc = blockIdx.x;
    int cg = bc & 255;
    int br = cg >> 6;
    int c  = cg & 63;
    size_t base = (size_t)bc * NPIX;
    const float* xp = x + base;
    unsigned* outp = g_yhl + base;
    switch (br) {
        case 0: dwconv_body<3>(xp, w3, b3, c, outp, st, ws); break;
        case 1: dwconv_body<5>(xp, w5, b5, c, outp, st, ws); break;
        case 2: dwconv_body<7>(xp, w7, b7, c, outp, st, ws); break;
        default: dwconv_body<9>(xp, w9, b9, c, outp, st, ws); break;
    }
}

// ---------------- tensor-core GEMM, templated A format --------------------
// AHL=1: A global/smem = packed hi/lo words (1 word per element); use hi only.
// AHL=0: A global/smem = fp16 (k,k+1)-pair words (1 word per 2 elements).
// 1 MMA per fragment pair. cp.async double-buffered. Staged epilogue.
template<int AHL>
__global__ __launch_bounds__(256) void gemm_cp(
    const unsigned* __restrict__ A, const unsigned* __restrict__ W,
    const float* __restrict__ bias,
    void* __restrict__ Cv, int K, long chunkA, long chunkC,
    int dosoftmax, int packout)
{
    constexpr int AROWS = AHL ? 32 : 16;     // smem word-rows per 32-k chunk
    constexpr int APS   = AHL ? 132 : 136;   // row stride in words (bank-verified)
    __shared__ __align__(16) unsigned Ap[2][AROWS][APS];
    __shared__ __align__(16) __half  Wh[2][64][40];

    int j0    = blockIdx.x * 64;
    int m0    = blockIdx.y * 128;
    int chunk = m0 >> 12;
    int mloc  = m0 & 4095;

    const unsigned* Ab = A + (size_t)chunk * chunkA + mloc;
    const unsigned* Wb = W + (size_t)j0 * K;
    float*    Cf = (float*)Cv    + (size_t)chunk * chunkC + mloc + (size_t)j0 * 4096;
    unsigned* Cp = (unsigned*)Cv + (size_t)chunk * chunkC + mloc + (size_t)j0 * 4096;

    int tid  = threadIdx.x;
    int wp   = tid >> 5;
    int lane = tid & 31;
    int g = lane >> 2, t4 = lane & 3;
    int warpm = wp & 3;
    int warpj = wp >> 2;
    int jf = tid >> 2;
    int kf = (tid & 3) * 8;

    float acc[2][4][4];
    #pragma unroll
    for (int mi = 0; mi < 2; mi++)
        #pragma unroll
        for (int ji = 0; ji < 4; ji++)
            #pragma unroll
            for (int cc = 0; cc < 4; cc++) acc[mi][ji][cc] = 0.f;

    int nchunk = K >> 5;
    constexpr int NFILL = AHL ? 4 : 2;       // cp16 ops per thread per chunk

    #pragma unroll
    for (int i = 0; i < NFILL; i++) {
        int o = tid + 256 * i;
        int k = o >> 5, mg = (o & 31) * 4;
        CP16(smem_u32(&Ap[0][k][mg]), Ab + (size_t)k * 4096 + mg);
    }
    CP_COMMIT;
    uint4 wv0 = *(const uint4*)(Wb + (size_t)jf * K + kf);
    uint4 wv1 = *(const uint4*)(Wb + (size_t)jf * K + kf + 4);

    int buf = 0;
    for (int c = 0; c < nchunk; c++) {
        uint4 uh;
        uh.x = __byte_perm(wv0.x, wv0.y, 0x5410);
        uh.y = __byte_perm(wv0.z, wv0.w, 0x5410);
        uh.z = __byte_perm(wv1.x, wv1.y, 0x5410);
        uh.w = __byte_perm(wv1.z, wv1.w, 0x5410);
        *(uint4*)&Wh[buf][jf][kf] = uh;
        CP_WAIT0;
        __syncthreads();
        if (c + 1 < nchunk) {
            int k0n = (c + 1) * AROWS;
            #pragma unroll
            for (int i = 0; i < NFILL; i++) {
                int o = tid + 256 * i;
                int k = o >> 5, mg = (o & 31) * 4;
                CP16(smem_u32(&Ap[buf ^ 1][k][mg]), Ab + (size_t)(k0n + k) * 4096 + mg);
            }
            CP_COMMIT;
            wv0 = *(const uint4*)(Wb + (size_t)jf * K + (c + 1) * 32 + kf);
            wv1 = *(const uint4*)(Wb + (size_t)jf * K + (c + 1) * 32 + kf + 4);
        }
        #pragma unroll
        for (int kk = 0; kk < 32; kk += 16) {
            unsigned ah[2][4];
            #pragma unroll
            for (int mi = 0; mi < 2; mi++) {
                int m = warpm * 32 + mi * 16 + g;
                if (AHL) {
                    int k1 = kk + 2 * t4;
                    unsigned w00 = Ap[buf][k1    ][m],     w01 = Ap[buf][k1 + 1][m];
                    unsigned w10 = Ap[buf][k1    ][m + 8], w11 = Ap[buf][k1 + 1][m + 8];
                    unsigned w20 = Ap[buf][k1 + 8][m],     w21 = Ap[buf][k1 + 9][m];
                    unsigned w30 = Ap[buf][k1 + 8][m + 8], w31 = Ap[buf][k1 + 9][m + 8];
                    ah[mi][0] = __byte_perm(w00, w01, 0x5410);
                    ah[mi][1] = __byte_perm(w10, w11, 0x5410);
                    ah[mi][2] = __byte_perm(w20, w21, 0x5410);
                    ah[mi][3] = __byte_perm(w30, w31, 0x5410);
                } else {
                    int k2 = (kk >> 1) + t4;
                    ah[mi][0] = Ap[buf][k2    ][m];
                    ah[mi][1] = Ap[buf][k2    ][m + 8];
                    ah[mi][2] = Ap[buf][k2 + 4][m];
                    ah[mi][3] = Ap[buf][k2 + 4][m + 8];
                }
            }
            unsigned bh[4][2];
            #pragma unroll
            for (int ji = 0; ji < 4; ji++) {
                int j = warpj * 32 + ji * 8 + g;
                bh[ji][0] = *(const unsigned*)&Wh[buf][j][kk + 2 * t4];
                bh[ji][1] = *(const unsigned*)&Wh[buf][j][kk + 2 * t4 + 8];
            }
            #pragma unroll
            for (int mi = 0; mi < 2; mi++)
                #pragma unroll
                for (int ji = 0; ji < 4; ji++)
                    mma16816(acc[mi][ji], ah[mi], bh[ji]);
        }
        __syncthreads();
        buf ^= 1;
    }

    float (*stage)[132] = (float(*)[132])Ap;
    int ksoft = dosoftmax && (j0 == 64);
    #pragma unroll
    for (int p = 0; p < 2; p++) {
        if (warpj == p) {
            #pragma unroll
            for (int mi = 0; mi < 2; mi++)
                #pragma unroll
                for (int ji = 0; ji < 4; ji++) {
                    int jr = ji * 8 + 2 * t4;
                    int m  = warpm * 32 + mi * 16 + g;
                    stage[jr    ][m    ] = acc[mi][ji][0];
                    stage[jr + 1][m    ] = acc[mi][ji][1];
                    stage[jr    ][m + 8] = acc[mi][ji][2];
                    stage[jr + 1][m + 8] = acc[mi][ji][3];
                }
        }
        __syncthreads();
        if (ksoft) {
            int hh = tid >> 7;
            int m  = tid & 127;
            float v[16];
            float mx = -3.4e38f;
            #pragma unroll
            for (int d = 0; d < 16; d++) { v[d] = stage[hh * 16 + d][m]; mx = fmaxf(mx, v[d]); }
            float ssum = 0.f;
            #pragma unroll
            for (int d = 0; d < 16; d++) { v[d] = __expf(v[d] - mx); ssum += v[d]; }
            float inv = 1.0f / ssum;
            #pragma unroll
            for (int d = 0; d < 16; d++)
                Cp[(size_t)(p * 32 + hh * 16 + d) * 4096 + m] = packhl(v[d] * inv);
        } else {
            #pragma unroll
            for (int r = 0; r < 4; r++) {
                int idx = r * 256 + tid;
                int jr  = idx >> 5;
                int m4  = (idx & 31) * 4;
                int jg  = p * 32 + jr;
                float bj = bias ? bias[j0 + jg] : 0.f;
                float4 v = *(const float4*)&stage[jr][m4];
                v.x += bj; v.y += bj; v.z += bj; v.w += bj;
                if (packout) {
                    uint4 u;
                    u.x = packhl(v.x); u.y = packhl(v.y);
                    u.z = packhl(v.z); u.w = packhl(v.w);
                    *(uint4*)(Cp + (size_t)jg * 4096 + m4) = u;
                } else {
                    *(float4*)(Cf + (size_t)jg * 4096 + m4) = v;
                }
            }
        }
        __syncthreads();
    }
}

// ---------------- q-stats: MZ = M + log(sum exp(q - M)) per column --------
__global__ __launch_bounds__(256) void qstats_kernel()
{
    __shared__ float red[256];
    int col = blockIdx.x;
    int bb = col >> 6, j = col & 63;
    const unsigned* base = g_qkvhl + ((size_t)(bb * 192 + j)) * 4096;
    int t = threadIdx.x;
    float v[16];
    float mx = -3.4e38f;
    #pragma unroll
    for (int i = 0; i < 16; i++) { v[i] = unpackf(base[t + i * 256]); mx = fmaxf(mx, v[i]); }
    red[t] = mx; __syncthreads();
    for (int s2 = 128; s2 > 0; s2 >>= 1) {
        if (t < s2) red[t] = fmaxf(red[t], red[t + s2]);
        __syncthreads();
    }
    mx = red[0]; __syncthreads();
    float sum = 0.f;
    #pragma unroll
    for (int i = 0; i < 16; i++) sum += __expf(v[i] - mx);
    red[t] = sum; __syncthreads();
    for (int s2 = 128; s2 > 0; s2 >>= 1) {
        if (t < s2) red[t] += red[t + s2];
        __syncthreads();
    }
    if (t == 0) g_MZ[col] = mx + __logf(red[0]);
}

// ---------------- context: C[d,e] = sum_n key[n,d] v[n,e] (un-normalized) -
__global__ __launch_bounds__(256) void context_kernel()
{
    __shared__ float ks[16][132];
    __shared__ float vs[16][132];
    int bh = blockIdx.x;
    int bb = bh >> 2, h = bh & 3;
    const unsigned* kb = g_qkvhl + ((size_t)(bb * 192 + 64  + h * 16)) * 4096;
    const unsigned* vb = g_qkvhl + ((size_t)(bb * 192 + 128 + h * 16)) * 4096;
    int t = threadIdx.x;
    int d = t >> 4, e = t & 15;
    float acc = 0.f;
    for (int n0 = 0; n0 < 4096; n0 += 128) {
        #pragma unroll
        for (int i = 0; i < 2; i++) {
            int idx = t * 2 + i;
            int row = idx >> 5;
            int c4  = (idx & 31) * 4;
            uint4 ku = *(const uint4*)(kb + (size_t)row * 4096 + n0 + c4);
            uint4 vu = *(const uint4*)(vb + (size_t)row * 4096 + n0 + c4);
            ks[row][c4 + 0] = unpackf(ku.x); ks[row][c4 + 1] = unpackf(ku.y);
            ks[row][c4 + 2] = unpackf(ku.z); ks[row][c4 + 3] = unpackf(ku.w);
            vs[row][c4 + 0] = unpackf(vu.x); vs[row][c4 + 1] = unpackf(vu.y);
            vs[row][c4 + 2] = unpackf(vu.z); vs[row][c4 + 3] = unpackf(vu.w);
        }
        __syncthreads();
        #pragma unroll
        for (int q4 = 0; q4 < 32; q4++) {
            float4 a = *(const float4*)&ks[d][q4 * 4];
            float4 b = *(const float4*)&vs[e][q4 * 4];
            acc += a.x * b.x + a.y * b.y + a.z * b.z + a.w * b.w;
        }
        __syncthreads();
    }
    g_ctx[(size_t)bh * 256 + d * 16 + e] = acc;
}

// ---------------- attn out: ao = exp(q - MZ) @ ctx, reshape folded --------
// stores fp16 channel-pair words: word(c2, n') = (h(ao[2c2]), h(ao[2c2+1]))
__global__ __launch_bounds__(256) void attnout_kernel()
{
    __shared__ float cs[1024];
    __shared__ float ms[64];
    int bb = blockIdx.x >> 4;
    int nt = blockIdx.x & 15;
    int t  = threadIdx.x;
    int n  = nt * 256 + t;
    if (t < 64) ms[t] = g_MZ[bb * 64 + t];
    for (int i = t; i < 1024; i += 256) cs[i] = g_ctx[(size_t)bb * 1024 + i];
    __syncthreads();
    const unsigned* qb = g_qkvhl + (size_t)bb * 192 * 4096 + n;
    int c2base = 8 * (n & 3);
    int pbase = n >> 2;
    for (int h = 0; h < 4; h++) {
        float acc[16];
        #pragma unroll
        for (int e = 0; e < 16; e++) acc[e] = 0.f;
        #pragma unroll
        for (int d = 0; d < 16; d++) {
            int jc = h * 16 + d;
            float qv = __expf(unpackf(qb[(size_t)jc * 4096]) - ms[jc]);
            const float4* crow = (const float4*)&cs[jc * 16];
            #pragma unroll
            for (int e4 = 0; e4 < 4; e4++) {
                float4 cv = crow[e4];
                acc[e4 * 4 + 0] += qv * cv.x;
                acc[e4 * 4 + 1] += qv * cv.y;
                acc[e4 * 4 + 2] += qv * cv.z;
                acc[e4 * 4 + 3] += qv * cv.w;
            }
        }
        int np = h * 1024 + pbase;
        #pragma unroll
        for (int e2 = 0; e2 < 8; e2++) {
            unsigned w = pack_h2(__float2half_rn(acc[2 * e2]),
                                 __float2half_rn(acc[2 * e2 + 1]));
            g_aoh2[((size_t)(bb * 32 + c2base + e2)) * 4096 + np] = w;
        }
    }
}

// ---------------- launch ---------------------------------------------------
extern "C" void kernel_launch(void* const* d_in, const int* in_sizes, int n_in,
                              void* d_out, int out_size)
{
    const float* x   = (const float*)d_in[0];
    const float* w3  = (const float*)d_in[1];
    const float* b3  = (const float*)d_in[2];
    const float* w5  = (const float*)d_in[3];
    const float* b5  = (const float*)d_in[4];
    const float* w7  = (const float*)d_in[5];
    const float* b7  = (const float*)d_in[6];
    const float* w9  = (const float*)d_in[7];
    const float* b9  = (const float*)d_in[8];
    const float* w_qkv   = (const float*)d_in[9];
    const float* w_proj  = (const float*)d_in[10];
    const float* b_proj  = (const float*)d_in[11];
    const float* w_final = (const float*)d_in[12];
    const float* b_final = (const float*)d_in[13];
    const float* scale_w = (const float*)d_in[14];
    float* out = (float*)d_out;

    unsigned *yp, *qkvp, *aop, *wcp, *wqp;
    float *cbp;
    cudaGetSymbolAddress((void**)&yp,   g_yhl);
    cudaGetSymbolAddress((void**)&qkvp, g_qkvhl);
    cudaGetSymbolAddress((void**)&aop,  g_aoh2);
    cudaGetSymbolAddress((void**)&wcp,  g_wchl);
    cudaGetSymbolAddress((void**)&wqp,  g_wqhl);
    cudaGetSymbolAddress((void**)&cbp,  g_cb);

    // 0. merged weight prep
    prep_kernel<<<304, 256>>>(w_qkv, w_proj, w_final, b_proj, b_final, scale_w);

    // 1. all 4 depthwise conv branches in one launch -> g_yhl (packed)
    dwconv_all<<<NB * NDIM, 256>>>(x, w3, b3, w5, b5, w7, b7, w9, b9);

    // 2. QKV GEMM (A packed-hl, hi only), fused K-softmax, packed out
    gemm_cp<1><<<dim3(3, 2048), 256>>>(yp, wqp, nullptr, qkvp,
                                       64, 64L * 4096, 192L * 4096, 1, 1);

    // 3. q-stats: MZ = M + logZ
    qstats_kernel<<<4096, 256>>>();

    // 4. context (un-normalized, conflict-free smem)
    context_kernel<<<256, 256>>>();

    // 5. attention out -> g_aoh2 (fp16 pairs, scrambled reshape layout)
    attnout_kernel<<<1024, 256>>>();

    // 6. fused proj+final GEMM (A fp16-pairs): out = Wc @ ao + cbias
    gemm_cp<0><<<dim3(4, 512), 256>>>(aop, wcp, cbp, out,
                                      256, 128L * 4096, 256L * 4096, 0, 0);
}